// round 6
// baseline (speedup 1.0000x reference)
#include <cuda_runtime.h>
#include <math.h>

#define T_DIM 2048
#define N_DIM 64
#define L_DIM 300
#define V_DIM 35
#define E_DIM 256
#define H_DIM 512
#define KS_DIM 128
#define VS_DIM 128

#define PRED_SIZE (N_DIM * L_DIM * V_DIM) /* 672000 */
#define ATT_SIZE  (N_DIM * L_DIM * T_DIM) /* 39321600 */

// ---- persistent device state (no allocations allowed) ----
#define S_H1  0
#define S_H2  (S_H1 + 2 * N_DIM * H_DIM)
#define S_C1  (S_H2 + 2 * N_DIM * H_DIM)
#define S_C2  (S_C1 + N_DIM * H_DIM)
#define S_H3  (S_C2 + N_DIM * H_DIM)
#define S_C3  (S_H3 + N_DIM * KS_DIM)
#define S_CTX (S_C3 + N_DIM * KS_DIM)
#define S_TOTAL (S_CTX + N_DIM * VS_DIM)

__device__ __align__(16) float g_state[S_TOTAL];
__device__ int g_text[N_DIM * L_DIM];
__device__ int g_flag;

__global__ void zero_kernel() {
    int i = blockIdx.x * blockDim.x + threadIdx.x;
    for (; i < S_TOTAL; i += gridDim.x * blockDim.x) g_state[i] = 0.f;
    if (blockIdx.x == 0 && threadIdx.x == 0) g_flag = 0;
}

// text may arrive as int64 (values 0..34 -> high 32-bit words all zero) or as
// int32 (JAX x64 disabled). Detect device-side: any nonzero odd 32-bit word
// within the first N*L words => int32.
__global__ void detect_kernel(const int* __restrict__ t32) {
    int i = blockIdx.x * blockDim.x + threadIdx.x;
    int idx = 2 * i + 1;
    if (idx < N_DIM * L_DIM && t32[idx] != 0) atomicOr(&g_flag, 1);
}

__global__ void decode_kernel(const int* __restrict__ t32) {
    int i = blockIdx.x * blockDim.x + threadIdx.x;
    if (i < N_DIM * L_DIM) g_text[i] = g_flag ? t32[i] : t32[2 * i];
}

// ---------------- LSTM layers 1 & 2 ----------------
// grid 128, block 256. Thread (u = tid/64, b = tid%64) computes all 4 gates of
// hidden unit j = blockIdx*4+u for batch b. Inputs staged into transposed SMEM
// s[k][b] (pitch 65 -> conflict free). Weight rows broadcast (uniform address
// per warp) as float4.
template <int LAYER>
__global__ __launch_bounds__(256) void lstm_kernel(
    const float* __restrict__ Wih, const float* __restrict__ Whh,
    const float* __restrict__ bih, const float* __restrict__ bhh,
    const float* __restrict__ emb_W, int l, int p)
{
    __shared__ float s[128][65];
    const int tid = threadIdx.x;
    const int b = tid & 63;
    const int u = tid >> 6;
    const int j = blockIdx.x * 4 + u;

    const int KIH = (LAYER == 1) ? 384 : 512;
    const int nIH = KIH >> 7;

    const float* hprev = g_state + ((LAYER == 1) ? S_H1 : S_H2) + p * (N_DIM * H_DIM);
    const float* inl   = (LAYER == 1) ? (const float*)0
                                      : (g_state + S_H1 + (p ^ 1) * (N_DIM * H_DIM));
    float* hnew = g_state + ((LAYER == 1) ? S_H1 : S_H2) + (p ^ 1) * (N_DIM * H_DIM);
    float* cbuf = g_state + ((LAYER == 1) ? S_C1 : S_C2);

    float acc0 = bih[j]            + bhh[j];
    float acc1 = bih[H_DIM + j]    + bhh[H_DIM + j];
    float acc2 = bih[2*H_DIM + j]  + bhh[2*H_DIM + j];
    float acc3 = bih[3*H_DIM + j]  + bhh[3*H_DIM + j];

    for (int c = 0; c < nIH + 4; ++c) {
        __syncthreads();
        // stage 64x128 input slab: v[b][k] -> s[k][b]
        for (int i4 = tid; i4 < 2048; i4 += 256) {
            int bb = i4 >> 5;
            int kk = (i4 & 31) << 2;
            float4 v;
            if (c < nIH) {
                int kg = c * 128 + kk;
                if (LAYER == 1) {
                    if (kg < 256) {
                        int tok = g_text[bb * L_DIM + l];
                        v = *(const float4*)(emb_W + tok * E_DIM + kg);
                    } else {
                        v = *(const float4*)(g_state + S_CTX + bb * VS_DIM + (kg - 256));
                    }
                } else {
                    v = *(const float4*)(inl + bb * H_DIM + kg);
                }
            } else {
                int kg = (c - nIH) * 128 + kk;
                v = *(const float4*)(hprev + bb * H_DIM + kg);
            }
            s[kk][bb] = v.x; s[kk + 1][bb] = v.y; s[kk + 2][bb] = v.z; s[kk + 3][bb] = v.w;
        }
        __syncthreads();

        const float* wb; int koff, wstr;
        if (c < nIH) { wb = Wih; koff = c * 128; wstr = KIH; }
        else         { wb = Whh; koff = (c - nIH) * 128; wstr = H_DIM; }
        const float* w0 = wb + (size_t)j * wstr + koff;
        const float* w1 = wb + (size_t)(H_DIM + j) * wstr + koff;
        const float* w2 = wb + (size_t)(2 * H_DIM + j) * wstr + koff;
        const float* w3 = wb + (size_t)(3 * H_DIM + j) * wstr + koff;

#pragma unroll 8
        for (int k = 0; k < 128; k += 4) {
            float4 wa = *(const float4*)(w0 + k);
            float4 wf = *(const float4*)(w1 + k);
            float4 wg = *(const float4*)(w2 + k);
            float4 wo = *(const float4*)(w3 + k);
            float x0 = s[k][b], x1 = s[k + 1][b], x2 = s[k + 2][b], x3 = s[k + 3][b];
            acc0 += wa.x * x0; acc0 += wa.y * x1; acc0 += wa.z * x2; acc0 += wa.w * x3;
            acc1 += wf.x * x0; acc1 += wf.y * x1; acc1 += wf.z * x2; acc1 += wf.w * x3;
            acc2 += wg.x * x0; acc2 += wg.y * x1; acc2 += wg.z * x2; acc2 += wg.w * x3;
            acc3 += wo.x * x0; acc3 += wo.y * x1; acc3 += wo.z * x2; acc3 += wo.w * x3;
        }
    }

    float ig = 1.f / (1.f + expf(-acc0));
    float fg = 1.f / (1.f + expf(-acc1));
    float gg = tanhf(acc2);
    float og = 1.f / (1.f + expf(-acc3));
    float cp = cbuf[b * H_DIM + j];
    float cn = fg * cp + ig * gg;
    cbuf[b * H_DIM + j] = cn;
    hnew[b * H_DIM + j] = og * tanhf(cn);
}

// ------- LSTM3 + attention (energy/softmax/context) + logits, fused -------
// One block per batch row (everything downstream of h2 is batch-local).
__global__ __launch_bounds__(512) void step3_kernel(
    const float* __restrict__ key, const float* __restrict__ values,
    const int* __restrict__ x_lens,
    const float* __restrict__ Wih3, const float* __restrict__ Whh3,
    const float* __restrict__ bih3, const float* __restrict__ bhh3,
    const float* __restrict__ emb_W, const float* __restrict__ b_out,
    float* __restrict__ out, int l, int p, int write_att)
{
    __shared__ __align__(16) float s_h2[512];
    __shared__ __align__(16) float s_h3p[128];
    __shared__ float s_g[512];
    __shared__ __align__(16) float s_h3[128];
    __shared__ float s_attn[2048];
    __shared__ __align__(16) float s_ctx[128];
    __shared__ float s_red[512];

    const int n = blockIdx.x;
    const int tid = threadIdx.x;
    const int w = tid >> 5, lane = tid & 31;

    s_h2[tid] = g_state[S_H2 + (p ^ 1) * (N_DIM * H_DIM) + n * H_DIM + tid];
    if (tid < 128) s_h3p[tid] = g_state[S_H3 + n * KS_DIM + tid];
    __syncthreads();

    // LSTM3 gates: 512 rows, 16 warps x 32 rows; warp-parallel dot over K=640
    for (int rr = 0; rr < 32; ++rr) {
        int r = w * 32 + rr;
        const float* wi = Wih3 + (size_t)r * 512;
        float sum = 0.f;
#pragma unroll
        for (int m = 0; m < 4; ++m) {
            float4 wv = *(const float4*)(wi + m * 128 + lane * 4);
            float4 xv = *(const float4*)(s_h2 + m * 128 + lane * 4);
            sum += wv.x * xv.x + wv.y * xv.y + wv.z * xv.z + wv.w * xv.w;
        }
        {
            float4 wv = *(const float4*)(Whh3 + (size_t)r * 128 + lane * 4);
            float4 xv = *(const float4*)(s_h3p + lane * 4);
            sum += wv.x * xv.x + wv.y * xv.y + wv.z * xv.z + wv.w * xv.w;
        }
#pragma unroll
        for (int o = 16; o > 0; o >>= 1) sum += __shfl_xor_sync(0xffffffffu, sum, o);
        if (lane == 0) s_g[r] = sum;
    }
    __syncthreads();

    if (tid < 128) {
        int jj = tid;
        float ai = s_g[jj]        + bih3[jj]        + bhh3[jj];
        float af = s_g[128 + jj]  + bih3[128 + jj]  + bhh3[128 + jj];
        float ag = s_g[256 + jj]  + bih3[256 + jj]  + bhh3[256 + jj];
        float ao = s_g[384 + jj]  + bih3[384 + jj]  + bhh3[384 + jj];
        float ig = 1.f / (1.f + expf(-ai));
        float fg = 1.f / (1.f + expf(-af));
        float gg = tanhf(ag);
        float og = 1.f / (1.f + expf(-ao));
        float cp = g_state[S_C3 + n * KS_DIM + jj];
        float cn = fg * cp + ig * gg;
        float hn = og * tanhf(cn);
        g_state[S_C3 + n * KS_DIM + jj] = cn;
        g_state[S_H3 + n * KS_DIM + jj] = hn;
        s_h3[jj] = hn;
    }
    __syncthreads();

    const int len = x_lens[n];
    const float4 hq = *(const float4*)(s_h3 + lane * 4);

    // energy over T (skip masked t -> halves key traffic on average); 2 t per
    // iteration for MLP
    for (int t = w; t < T_DIM; t += 32) {
        int t2 = t + 16;
        float e1 = -1e9f, e2 = -1e9f;
        if (t < len) {
            float4 kv = *(const float4*)(key + ((size_t)t * N_DIM + n) * KS_DIM + lane * 4);
            e1 = kv.x * hq.x + kv.y * hq.y + kv.z * hq.z + kv.w * hq.w;
        }
        if (t2 < len) {
            float4 kv = *(const float4*)(key + ((size_t)t2 * N_DIM + n) * KS_DIM + lane * 4);
            e2 = kv.x * hq.x + kv.y * hq.y + kv.z * hq.z + kv.w * hq.w;
        }
#pragma unroll
        for (int o = 16; o > 0; o >>= 1) {
            e1 += __shfl_xor_sync(0xffffffffu, e1, o);
            e2 += __shfl_xor_sync(0xffffffffu, e2, o);
        }
        if (t >= len)  e1 = -1e9f;
        if (t2 >= len) e2 = -1e9f;
        if (lane == 0) { s_attn[t] = e1; s_attn[t2] = e2; }
    }
    __syncthreads();

    // softmax (block reductions)
    float mx = -3.4e38f;
    for (int t = tid; t < T_DIM; t += 512) mx = fmaxf(mx, s_attn[t]);
    s_red[tid] = mx; __syncthreads();
#pragma unroll
    for (int off = 256; off > 0; off >>= 1) {
        if (tid < off) s_red[tid] = fmaxf(s_red[tid], s_red[tid + off]);
        __syncthreads();
    }
    mx = s_red[0];
    __syncthreads();

    float sm = 0.f;
    for (int t = tid; t < T_DIM; t += 512) {
        float pe = expf(s_attn[t] - mx);
        s_attn[t] = pe;
        sm += pe;
    }
    s_red[tid] = sm; __syncthreads();
#pragma unroll
    for (int off = 256; off > 0; off >>= 1) {
        if (tid < off) s_red[tid] += s_red[tid + off];
        __syncthreads();
    }
    float inv = 1.f / s_red[0];
    __syncthreads();

    float* att_out = out + PRED_SIZE + ((size_t)n * L_DIM + l) * T_DIM;
    for (int t = tid; t < T_DIM; t += 512) {
        float a = s_attn[t] * inv;
        s_attn[t] = a;
        if (write_att) att_out[t] = a;
    }
    __syncthreads();

    // context: 4 t-groups x 128 e; masked t have attn==0 -> skip values reads
    {
        int gi = tid >> 7, e = tid & 127;
        float acc = 0.f;
#pragma unroll 4
        for (int t = gi; t < len; t += 4)
            acc += s_attn[t] * __ldg(values + ((size_t)t * N_DIM + n) * VS_DIM + e);
        s_red[tid] = acc;
        __syncthreads();
        if (tid < 128) {
            float cx = s_red[tid] + s_red[128 + tid] + s_red[256 + tid] + s_red[384 + tid];
            s_ctx[tid] = cx;
            g_state[S_CTX + n * VS_DIM + tid] = cx;
        }
    }
    __syncthreads();

    // logits: 35 rows, K=256 = [h3 || ctx]
    for (int r = w; r < V_DIM; r += 16) {
        const float* er = emb_W + (size_t)r * E_DIM;
        float4 w1 = *(const float4*)(er + lane * 4);
        float4 w2 = *(const float4*)(er + 128 + lane * 4);
        float4 x1 = *(const float4*)(s_h3 + lane * 4);
        float4 x2 = *(const float4*)(s_ctx + lane * 4);
        float sum = w1.x * x1.x + w1.y * x1.y + w1.z * x1.z + w1.w * x1.w
                  + w2.x * x2.x + w2.y * x2.y + w2.z * x2.z + w2.w * x2.w;
#pragma unroll
        for (int o = 16; o > 0; o >>= 1) sum += __shfl_xor_sync(0xffffffffu, sum, o);
        if (lane == 0) out[((size_t)n * L_DIM + l) * V_DIM + r] = sum + b_out[r];
    }
}

extern "C" void kernel_launch(void* const* d_in, const int* in_sizes, int n_in,
                              void* d_out, int out_size) {
    const float* key    = (const float*)d_in[0];
    const float* values = (const float*)d_in[1];
    const int*   x_lens = (const int*)d_in[2];
    const int*   text32 = (const int*)d_in[3];
    const float* emb_W  = (const float*)d_in[4];
    const float* Wih1 = (const float*)d_in[5];
    const float* Whh1 = (const float*)d_in[6];
    const float* bih1 = (const float*)d_in[7];
    const float* bhh1 = (const float*)d_in[8];
    const float* Wih2 = (const float*)d_in[9];
    const float* Whh2 = (const float*)d_in[10];
    const float* bih2 = (const float*)d_in[11];
    const float* bhh2 = (const float*)d_in[12];
    const float* Wih3 = (const float*)d_in[13];
    const float* Whh3 = (const float*)d_in[14];
    const float* bih3 = (const float*)d_in[15];
    const float* bhh3 = (const float*)d_in[16];
    const float* b_out = (const float*)d_in[17];
    float* out = (float*)d_out;

    int write_att = (out_size >= PRED_SIZE + ATT_SIZE) ? 1 : 0;

    zero_kernel<<<216, 256>>>();
    detect_kernel<<<(N_DIM * L_DIM / 2 + 255) / 256, 256>>>(text32);
    decode_kernel<<<(N_DIM * L_DIM + 255) / 256, 256>>>(text32);

    for (int l = 0; l < L_DIM; ++l) {
        int p = l & 1;
        lstm_kernel<1><<<128, 256>>>(Wih1, Whh1, bih1, bhh1, emb_W, l, p);
        lstm_kernel<2><<<128, 256>>>(Wih2, Whh2, bih2, bhh2, emb_W, l, p);
        step3_kernel<<<64, 512>>>(key, values, x_lens, Wih3, Whh3, bih3, bhh3,
                                  emb_W, b_out, out, l, p, write_att);
    }
}

// round 8
// speedup vs baseline: 1.6489x; 1.6489x over previous
#include <cuda_runtime.h>
#include <math.h>

typedef unsigned long long u64;

#define T_DIM 2048
#define N_DIM 64
#define L_DIM 300
#define V_DIM 35
#define E_DIM 256
#define H_DIM 512
#define KS_DIM 128
#define VS_DIM 128

#define PRED_SIZE (N_DIM * L_DIM * V_DIM)
#define ATT_SIZE  (N_DIM * L_DIM * T_DIM)
#define NH (N_DIM * H_DIM)
#define NK (N_DIM * KS_DIM)

// ---- persistent device state (no allocations allowed) ----
#define S_H1  0
#define S_H2  (S_H1 + 2 * NH)
#define S_C1  (S_H2 + 2 * NH)
#define S_C2  (S_C1 + NH)
#define S_H3  (S_C2 + NH)
#define S_C3  (S_H3 + 2 * NK)
#define S_CTX (S_C3 + NK)
#define S_TOTAL (S_CTX + NK)

__device__ __align__(16) float g_state[S_TOTAL];
__device__ __align__(16) float g_emb[V_DIM * 2048];   // Wih1[:, :256]@emb[v] + bih1 + bhh1
__device__ float g_pw[N_DIM * T_DIM];                 // unnormalized softmax numerators
__device__ float g_cw[N_DIM * 4 * KS_DIM];            // per-slice partial context
__device__ float g_ms[N_DIM * 4];
__device__ float g_ls[N_DIM * 4];
__device__ int g_text[N_DIM * L_DIM];
__device__ int g_flag;

// grid barrier state
__device__ unsigned g_count;
__device__ volatile unsigned g_sense;

__device__ __forceinline__ u64 ffma2(u64 a, u64 b, u64 c) {
    u64 d;
    asm("fma.rn.f32x2 %0, %1, %2, %3;" : "=l"(d) : "l"(a), "l"(b), "l"(c));
    return d;
}
__device__ __forceinline__ float f2sum(u64 a) {
    float x, y;
    asm("mov.b64 {%0, %1}, %2;" : "=f"(x), "=f"(y) : "l"(a));
    return x + y;
}
__device__ __forceinline__ float4 ldcg4(const float* p) {
    return __ldcg((const float4*)p);
}

__device__ __forceinline__ void gbar(unsigned& lsense) {
    __syncthreads();
    if (threadIdx.x == 0) {
        lsense ^= 1u;
        __threadfence();
        if (atomicAdd(&g_count, 1u) == gridDim.x - 1) {
            g_count = 0;
            __threadfence();
            g_sense = lsense;
        } else {
            while (g_sense != lsense) __nanosleep(64);
        }
    }
    __syncthreads();
}

// ---------------- prologue kernels ----------------
__global__ void zero_kernel() {
    int i = blockIdx.x * blockDim.x + threadIdx.x;
    for (; i < S_TOTAL; i += gridDim.x * blockDim.x) g_state[i] = 0.f;
    if (blockIdx.x == 0 && threadIdx.x == 0) { g_flag = 0; g_count = 0; g_sense = 0; }
}
__global__ void detect_kernel(const int* __restrict__ t32) {
    int i = blockIdx.x * blockDim.x + threadIdx.x;
    int idx = 2 * i + 1;
    if (idx < N_DIM * L_DIM && t32[idx] != 0) atomicOr(&g_flag, 1);
}
__global__ void decode_kernel(const int* __restrict__ t32) {
    int i = blockIdx.x * blockDim.x + threadIdx.x;
    if (i < N_DIM * L_DIM) g_text[i] = g_flag ? t32[i] : t32[2 * i];
}
// g_emb[v][r] = Wih1[r, :256] @ emb[v] + bih1[r] + bhh1[r]
__global__ __launch_bounds__(256) void emb_kernel(
    const float* __restrict__ emb_W, const float* __restrict__ Wih1,
    const float* __restrict__ bih1, const float* __restrict__ bhh1)
{
    int r = blockIdx.x * 256 + threadIdx.x;
    int v = blockIdx.y;
    const float* w = Wih1 + (size_t)r * 384;
    const float* e = emb_W + (size_t)v * E_DIM;
    float acc = bih1[r] + bhh1[r];
#pragma unroll 8
    for (int k = 0; k < 256; ++k) acc += w[k] * e[k];
    g_emb[v * 2048 + r] = acc;
}

// ---------------- phase device functions ----------------

// Layers 1 & 2: bid<128 blocks, 4 units each. Thread (su=tid>>7, g=(tid>>5)&3,
// b2=tid&31) computes gate row g of unit bid*4+su for batches b2 and b2+32.
template <int LAYER>
__device__ void mm12_phase(
    float4 (*s4)[65], float (*s_fin)[4][64],
    const float* __restrict__ Wih, const float* __restrict__ Whh,
    const float* __restrict__ bih, const float* __restrict__ bhh,
    int l, int p, int bid, int tid)
{
    if (bid >= 128) return;
    constexpr int NSEG = (LAYER == 1) ? 5 : 8;
    const int su = tid >> 7;
    const int g = (tid >> 5) & 3;
    const int b2 = tid & 31;
    const int j = bid * 4 + su;
    const int r = g * 512 + j;

    u64 a0 = 0, a1 = 0, c0 = 0, c1 = 0;
    for (int c = 0; c < NSEG; ++c) {
        __syncthreads();
#pragma unroll
        for (int it = 0; it < 4; ++it) {
            int i4 = tid + it * 512;
            int bb = i4 >> 5, q = i4 & 31;
            const float* src;
            if (LAYER == 1)
                src = (c == 0) ? g_state + S_CTX + bb * 128
                               : g_state + S_H1 + p * NH + bb * 512 + (c - 1) * 128;
            else
                src = (c < 4) ? g_state + S_H1 + (p ^ 1) * NH + bb * 512 + c * 128
                              : g_state + S_H2 + p * NH + bb * 512 + (c - 4) * 128;
            s4[q][bb] = ldcg4(src + q * 4);
        }
        __syncthreads();
        const float* w;
        if (LAYER == 1)
            w = (c == 0) ? Wih + (size_t)r * 384 + 256
                         : Whh + (size_t)r * 512 + (c - 1) * 128;
        else
            w = (c < 4) ? Wih + (size_t)r * 512 + c * 128
                        : Whh + (size_t)r * 512 + (c - 4) * 128;
        const ulonglong2* W = (const ulonglong2*)w;
#pragma unroll
        for (int q = 0; q < 32; ++q) {
            ulonglong2 wv = W[q];
            ulonglong2 x0 = *(const ulonglong2*)&s4[q][b2];
            ulonglong2 x1 = *(const ulonglong2*)&s4[q][b2 + 32];
            a0 = ffma2(wv.x, x0.x, a0); a1 = ffma2(wv.y, x0.y, a1);
            c0 = ffma2(wv.x, x1.x, c0); c1 = ffma2(wv.y, x1.y, c1);
        }
    }
    s_fin[su][g][b2] = f2sum(a0) + f2sum(a1);
    s_fin[su][g][b2 + 32] = f2sum(c0) + f2sum(c1);
    __syncthreads();
    if (tid < 256) {
        int fu = tid >> 6, b = tid & 63;
        int fj = bid * 4 + fu;
        float s0 = s_fin[fu][0][b], s1 = s_fin[fu][1][b];
        float s2 = s_fin[fu][2][b], s3 = s_fin[fu][3][b];
        if (LAYER == 1) {
            int tok = g_text[b * L_DIM + l];
            const float* e = g_emb + tok * 2048;
            s0 += e[fj]; s1 += e[512 + fj]; s2 += e[1024 + fj]; s3 += e[1536 + fj];
        } else {
            s0 += bih[fj] + bhh[fj];
            s1 += bih[512 + fj] + bhh[512 + fj];
            s2 += bih[1024 + fj] + bhh[1024 + fj];
            s3 += bih[1536 + fj] + bhh[1536 + fj];
        }
        float ig = 1.f / (1.f + expf(-s0));
        float fg = 1.f / (1.f + expf(-s1));
        float gg = tanhf(s2);
        float og = 1.f / (1.f + expf(-s3));
        float* cb = g_state + ((LAYER == 1) ? S_C1 : S_C2) + b * 512 + fj;
        float cn = fg * (*cb) + ig * gg;
        *cb = cn;
        g_state[((LAYER == 1) ? S_H1 : S_H2) + (p ^ 1) * NH + b * 512 + fj] = og * tanhf(cn);
    }
}

// Layer 3: bid<64 blocks, 2 units each. Thread (su=tid>>8, g=(tid>>6)&3, b=tid&63).
__device__ void mm3_phase(
    float4 (*s4)[65], float (*s_fin)[4][64],
    const float* __restrict__ Wih3, const float* __restrict__ Whh3,
    const float* __restrict__ bih3, const float* __restrict__ bhh3,
    int p, int bid, int tid)
{
    if (bid >= 64) return;
    const int su = tid >> 8;
    const int g = (tid >> 6) & 3;
    const int b = tid & 63;
    const int j = bid * 2 + su;
    const int r = g * 128 + j;

    u64 a0 = 0, a1 = 0;
    for (int c = 0; c < 5; ++c) {
        __syncthreads();
#pragma unroll
        for (int it = 0; it < 4; ++it) {
            int i4 = tid + it * 512;
            int bb = i4 >> 5, q = i4 & 31;
            const float* src = (c < 4)
                ? g_state + S_H2 + (p ^ 1) * NH + bb * 512 + c * 128
                : g_state + S_H3 + p * NK + bb * 128;
            s4[q][bb] = ldcg4(src + q * 4);
        }
        __syncthreads();
        const float* w = (c < 4) ? Wih3 + (size_t)r * 512 + c * 128
                                 : Whh3 + (size_t)r * 128;
        const ulonglong2* W = (const ulonglong2*)w;
#pragma unroll
        for (int q = 0; q < 32; ++q) {
            ulonglong2 wv = W[q];
            ulonglong2 xv = *(const ulonglong2*)&s4[q][b];
            a0 = ffma2(wv.x, xv.x, a0);
            a1 = ffma2(wv.y, xv.y, a1);
        }
    }
    s_fin[su][g][b] = f2sum(a0) + f2sum(a1);
    __syncthreads();
    if (tid < 128) {
        int fu = tid >> 6, fb = tid & 63;
        int fj = bid * 2 + fu;
        float s0 = s_fin[fu][0][fb] + bih3[fj] + bhh3[fj];
        float s1 = s_fin[fu][1][fb] + bih3[128 + fj] + bhh3[128 + fj];
        float s2 = s_fin[fu][2][fb] + bih3[256 + fj] + bhh3[256 + fj];
        float s3 = s_fin[fu][3][fb] + bih3[384 + fj] + bhh3[384 + fj];
        float ig = 1.f / (1.f + expf(-s0));
        float fg = 1.f / (1.f + expf(-s1));
        float gg = tanhf(s2);
        float og = 1.f / (1.f + expf(-s3));
        float* cb = g_state + S_C3 + fb * 128 + fj;
        float cn = fg * (*cb) + ig * gg;
        *cb = cn;
        g_state[S_H3 + (p ^ 1) * NK + fb * 128 + fj] = og * tanhf(cn);
    }
}

// attention: 256 tasks = (slice s<4 of 512 t, batch n). Streams key/values with
// __ldcs (evict-first) so LSTM weights stay L1-resident.
__device__ void attn_phase(
    float* s_e, float* s_p, float* s_red, float* s_h3,
    const float* __restrict__ key, const float* __restrict__ values,
    const int* __restrict__ x_lens, int p, int bid, int tid)
{
    const int w = tid >> 5, lane = tid & 31;
    for (int tk = bid; tk < 256; tk += gridDim.x) {
        const int n = tk & 63, s = tk >> 6;
        const int t0 = s * 512;
        __syncthreads();
        if (tid < 128) s_h3[tid] = __ldcg(g_state + S_H3 + (p ^ 1) * NK + n * 128 + tid);
        s_e[tid] = -3.0e38f;
        __syncthreads();

        const int len = x_lens[n];
        const int tc = min(len - t0, 512);
        const ulonglong2 h3r = ((const ulonglong2*)s_h3)[lane];

        const int base = w * 32;
        const int lim = min(tc, base + 32);
#pragma unroll 2
        for (int tl = base; tl < lim; ++tl) {
            ulonglong2 kv = __ldcs((const ulonglong2*)(key +
                ((size_t)(t0 + tl) * N_DIM + n) * KS_DIM) + lane);
            float e = f2sum(ffma2(kv.y, h3r.y, ffma2(kv.x, h3r.x, 0ULL)));
#pragma unroll
            for (int o = 16; o > 0; o >>= 1) e += __shfl_xor_sync(0xffffffffu, e, o);
            if (lane == 0) s_e[tl] = e;
        }
        __syncthreads();

        float m = s_e[tid];
        s_red[tid] = m; __syncthreads();
#pragma unroll
        for (int off = 256; off > 0; off >>= 1) {
            if (tid < off) s_red[tid] = fmaxf(s_red[tid], s_red[tid + off]);
            __syncthreads();
        }
        m = s_red[0];
        __syncthreads();

        float pv = (tid < tc) ? expf(s_e[tid] - m) : 0.f;
        s_p[tid] = pv;
        g_pw[n * T_DIM + t0 + tid] = pv;
        s_red[tid] = pv; __syncthreads();
#pragma unroll
        for (int off = 256; off > 0; off >>= 1) {
            if (tid < off) s_red[tid] += s_red[tid + off];
            __syncthreads();
        }
        if (tid == 0) { g_ms[n * 4 + s] = m; g_ls[n * 4 + s] = s_red[0]; }
        __syncthreads();

        // partial context: (e = tid&127, h = tid>>7) 4-way t-split
        {
            int e = tid & 127, h = tid >> 7;
            float acc = 0.f;
#pragma unroll 4
            for (int t = h; t < tc; t += 4)
                acc += s_p[t] * __ldcs(values + ((size_t)(t0 + t) * N_DIM + n) * VS_DIM + e);
            s_red[tid] = acc;
            __syncthreads();
            if (tid < 128)
                g_cw[(n * 4 + s) * KS_DIM + tid] =
                    s_red[tid] + s_red[128 + tid] + s_red[256 + tid] + s_red[384 + tid];
        }
    }
}

__device__ void combine_phase(
    float* s_h3, float* s_ctx, float* s_scale,
    const float* __restrict__ emb_W, const float* __restrict__ b_out,
    float* __restrict__ out, int l, int p, int write_att, int bid, int tid)
{
    if (bid >= 64) return;
    const int n = bid;
    const int w = tid >> 5, lane = tid & 31;

    if (tid == 0) {
        float m0 = __ldcg(g_ms + n * 4 + 0), m1 = __ldcg(g_ms + n * 4 + 1);
        float m2 = __ldcg(g_ms + n * 4 + 2), m3 = __ldcg(g_ms + n * 4 + 3);
        float M = fmaxf(fmaxf(m0, m1), fmaxf(m2, m3));
        float e0 = expf(m0 - M), e1 = expf(m1 - M), e2 = expf(m2 - M), e3 = expf(m3 - M);
        float Z = __ldcg(g_ls + n * 4 + 0) * e0 + __ldcg(g_ls + n * 4 + 1) * e1
                + __ldcg(g_ls + n * 4 + 2) * e2 + __ldcg(g_ls + n * 4 + 3) * e3;
        float iz = 1.f / Z;
        s_scale[0] = e0 * iz; s_scale[1] = e1 * iz;
        s_scale[2] = e2 * iz; s_scale[3] = e3 * iz;
    }
    if (tid < 128) s_h3[tid] = __ldcg(g_state + S_H3 + (p ^ 1) * NK + n * 128 + tid);
    __syncthreads();

    if (write_att) {
        float* att = out + PRED_SIZE + ((size_t)n * L_DIM + l) * T_DIM;
#pragma unroll
        for (int i = tid; i < T_DIM; i += 512)
            att[i] = __ldcg(g_pw + n * T_DIM + i) * s_scale[i >> 9];
    }
    if (tid < 128) {
        float cx = __ldcg(g_cw + (n * 4 + 0) * KS_DIM + tid) * s_scale[0]
                 + __ldcg(g_cw + (n * 4 + 1) * KS_DIM + tid) * s_scale[1]
                 + __ldcg(g_cw + (n * 4 + 2) * KS_DIM + tid) * s_scale[2]
                 + __ldcg(g_cw + (n * 4 + 3) * KS_DIM + tid) * s_scale[3];
        s_ctx[tid] = cx;
        g_state[S_CTX + n * 128 + tid] = cx;
    }
    __syncthreads();

    for (int r = w; r < V_DIM; r += 16) {
        const float* er = emb_W + (size_t)r * E_DIM;
        float4 w1 = *(const float4*)(er + lane * 4);
        float4 w2 = *(const float4*)(er + 128 + lane * 4);
        float4 x1 = *(const float4*)(s_h3 + lane * 4);
        float4 x2 = *(const float4*)(s_ctx + lane * 4);
        float sum = w1.x * x1.x + w1.y * x1.y + w1.z * x1.z + w1.w * x1.w
                  + w2.x * x2.x + w2.y * x2.y + w2.z * x2.z + w2.w * x2.w;
#pragma unroll
        for (int o = 16; o > 0; o >>= 1) sum += __shfl_xor_sync(0xffffffffu, sum, o);
        if (lane == 0) out[((size_t)n * L_DIM + l) * V_DIM + r] = sum + b_out[r];
    }
}

// ---------------- the persistent kernel ----------------
__global__ __launch_bounds__(512) void decoder_kernel(
    const float* __restrict__ key, const float* __restrict__ values,
    const int* __restrict__ x_lens,
    const float* __restrict__ emb_W,
    const float* __restrict__ Wih1, const float* __restrict__ Whh1,
    const float* __restrict__ Wih2, const float* __restrict__ Whh2,
    const float* __restrict__ bih2, const float* __restrict__ bhh2,
    const float* __restrict__ Wih3, const float* __restrict__ Whh3,
    const float* __restrict__ bih3, const float* __restrict__ bhh3,
    const float* __restrict__ b_out,
    float* __restrict__ out, int write_att)
{
    __shared__ float4 s4[32][65];
    __shared__ float s_fin[4][4][64];
    __shared__ float s_e[512];
    __shared__ float s_p[512];
    __shared__ float s_red[512];
    __shared__ float s_h3[128];
    __shared__ float s_ctx[128];
    __shared__ float s_scale[4];

    const int bid = blockIdx.x;
    const int tid = threadIdx.x;
    unsigned lsense = 0;

#pragma unroll 1
    for (int l = 0; l < L_DIM; ++l) {
        const int p = l & 1;
        mm12_phase<1>(s4, s_fin, Wih1, Whh1, (const float*)0, (const float*)0, l, p, bid, tid);
        gbar(lsense);
        mm12_phase<2>(s4, s_fin, Wih2, Whh2, bih2, bhh2, l, p, bid, tid);
        gbar(lsense);
        mm3_phase(s4, s_fin, Wih3, Whh3, bih3, bhh3, p, bid, tid);
        gbar(lsense);
        attn_phase(s_e, s_p, s_red, s_h3, key, values, x_lens, p, bid, tid);
        gbar(lsense);
        combine_phase(s_h3, s_ctx, s_scale, emb_W, b_out, out, l, p, write_att, bid, tid);
        gbar(lsense);
    }
}

extern "C" void kernel_launch(void* const* d_in, const int* in_sizes, int n_in,
                              void* d_out, int out_size) {
    const float* key    = (const float*)d_in[0];
    const float* values = (const float*)d_in[1];
    const int*   x_lens = (const int*)d_in[2];
    const int*   text32 = (const int*)d_in[3];
    const float* emb_W  = (const float*)d_in[4];
    const float* Wih1 = (const float*)d_in[5];
    const float* Whh1 = (const float*)d_in[6];
    const float* bih1 = (const float*)d_in[7];
    const float* bhh1 = (const float*)d_in[8];
    const float* Wih2 = (const float*)d_in[9];
    const float* Whh2 = (const float*)d_in[10];
    const float* bih2 = (const float*)d_in[11];
    const float* bhh2 = (const float*)d_in[12];
    const float* Wih3 = (const float*)d_in[13];
    const float* Whh3 = (const float*)d_in[14];
    const float* bih3 = (const float*)d_in[15];
    const float* bhh3 = (const float*)d_in[16];
    const float* b_out = (const float*)d_in[17];
    float* out = (float*)d_out;

    int write_att = (out_size >= PRED_SIZE + ATT_SIZE) ? 1 : 0;

    int dev = 0, nsm = 148;
    cudaGetDevice(&dev);
    cudaDeviceGetAttribute(&nsm, cudaDevAttrMultiProcessorCount, dev);
    if (nsm < 128) nsm = 128;   // phase mappings need >=128 co-resident blocks

    zero_kernel<<<216, 256>>>();
    detect_kernel<<<(N_DIM * L_DIM / 2 + 255) / 256, 256>>>(text32);
    decode_kernel<<<(N_DIM * L_DIM + 255) / 256, 256>>>(text32);
    emb_kernel<<<dim3(8, V_DIM), 256>>>(emb_W, Wih1, bih1, bhh1);

    decoder_kernel<<<nsm, 512>>>(key, values, x_lens, emb_W,
                                 Wih1, Whh1, Wih2, Whh2, bih2, bhh2,
                                 Wih3, Whh3, bih3, bhh3, b_out,
                                 out, write_att);
}